// round 13
// baseline (speedup 1.0000x reference)
#include <cuda_runtime.h>
#include <cstdint>

// ---------------------------------------------------------------------------
// ChordProgressionLoss v13 — bulk-async (TMA-engine) smem staging.
// Diagnosis R2-R12: all register-MLP variants pin at 2.3TB/s (29% HBM) —
// per-warp scoreboard limits loads in flight. Fix: cp.async.bulk 1D copies
// stream 931-row tiles (pred+targ) into double-buffered smem via mbarrier;
// 32 warps process from smem (LDS.128, conflict-free). Math unchanged:
// f32x2 magic masks, PRMT jaccard bytes, 3 shuffles + dp4a windows, integer
// max, fixed-point sim; exact integer sums -> deterministic atomics.
// Stale tail rows in smem are sanitized by clamping p,q (accumulation is
// already guarded by global row bounds).
// ---------------------------------------------------------------------------

#define NBLK 296
#define THREADS 1024
#define WPB 32
#define TILE_ROWS 928            // 32 warps x 29 rows
#define COPY_ROWS 931            // +3 for window overlap
#define TILE_BYTES 14912         // 931*16 = 14896, padded to 16B multiple
#define DYN_SMEM (4 * TILE_BYTES)  // 2 buffers x (pred+targ)

__device__ unsigned long long g_simSlots[32];
__device__ unsigned long long g_penSlots[32];
__device__ unsigned int       g_count = 0;

#define MAGIC2  0x4B4000004B400000ULL
#define INV12_2 0x3DAAAAAB3DAAAAABULL
#define BIAS2   0xBEEAAAABBEEAAAABULL

__device__ __forceinline__ uint32_t smem_u32(const void* p) {
    uint32_t a;
    asm("{ .reg .u64 t; cvta.to.shared.u64 t, %1; cvt.u32.u64 %0, t; }"
        : "=r"(a) : "l"(p));
    return a;
}
__device__ __forceinline__ void mbar_init(uint32_t mbar, unsigned cnt) {
    asm volatile("mbarrier.init.shared.b64 [%0], %1;" :: "r"(mbar), "r"(cnt) : "memory");
}
__device__ __forceinline__ void mbar_expect_tx(uint32_t mbar, unsigned bytes) {
    asm volatile("mbarrier.arrive.expect_tx.shared.b64 _, [%0], %1;"
                 :: "r"(mbar), "r"(bytes) : "memory");
}
__device__ __forceinline__ void mbar_wait(uint32_t mbar, unsigned phase) {
    asm volatile(
        "{\n\t.reg .pred P;\n\t"
        "W_%=:\n\t"
        "mbarrier.try_wait.parity.acquire.cta.shared::cta.b64 P, [%0], %1, 10000000;\n\t"
        "@!P bra W_%=;\n\t}"
        :: "r"(mbar), "r"(phase) : "memory");
}
__device__ __forceinline__ void bulk_copy(uint32_t dst, const void* src,
                                          unsigned bytes, uint32_t mbar) {
    asm volatile(
        "cp.async.bulk.shared::cta.global.mbarrier::complete_tx::bytes [%0], [%1], %2, [%3];"
        :: "r"(dst), "l"(src), "r"(bytes), "r"(mbar) : "memory");
}
__device__ __forceinline__ void fence_async() {
    asm volatile("fence.proxy.async;" ::: "memory");
}

__device__ __forceinline__ unsigned pcmask(float4 v) {
    unsigned long long dxy, dzw, b1xy, b1zw, t, b2xy, b2zw;
    asm("mov.b64 %0, {%1,%2};" : "=l"(dxy) : "f"(v.x), "f"(v.y));
    asm("mov.b64 %0, {%1,%2};" : "=l"(dzw) : "f"(v.z), "f"(v.w));
    asm("add.rn.f32x2 %0, %1, %2;" : "=l"(b1xy) : "l"(dxy), "l"(MAGIC2));
    asm("add.rn.f32x2 %0, %1, %2;" : "=l"(b1zw) : "l"(dzw), "l"(MAGIC2));
    asm("fma.rn.f32x2 %0, %1, %2, %3;" : "=l"(t) : "l"(dxy), "l"(INV12_2), "l"(BIAS2));
    asm("add.rn.f32x2 %0, %1, %2;" : "=l"(b2xy) : "l"(t), "l"(MAGIC2));
    asm("fma.rn.f32x2 %0, %1, %2, %3;" : "=l"(t) : "l"(dzw), "l"(INV12_2), "l"(BIAS2));
    asm("add.rn.f32x2 %0, %1, %2;" : "=l"(b2zw) : "l"(t), "l"(MAGIC2));
    unsigned a0, a1, a2, a3, q0, q1, q2, q3;
    asm("mov.b64 {%0,%1}, %2;" : "=r"(a0), "=r"(a1) : "l"(b1xy));
    asm("mov.b64 {%0,%1}, %2;" : "=r"(a2), "=r"(a3) : "l"(b1zw));
    asm("mov.b64 {%0,%1}, %2;" : "=r"(q0), "=r"(q1) : "l"(b2xy));
    asm("mov.b64 {%0,%1}, %2;" : "=r"(q2), "=r"(q3) : "l"(b2zw));
    return (1u << ((a0 - 12u * q0) & 31u))
         | (1u << ((a1 - 12u * q1) & 31u))
         | (1u << ((a2 - 12u * q2) & 31u))
         | (1u << ((a3 - 12u * q3) & 31u));
}

extern __shared__ char dynS[];

__global__ __launch_bounds__(THREADS, 2) void chord_fused(
    const float4* __restrict__ pred, const float4* __restrict__ targ,
    float* __restrict__ out, int T, int nTiles)
{
    __shared__ unsigned sT60[5];
    __shared__ uint2    sSim[21];
    __shared__ unsigned long long redS[WPB], redP[WPB];
    __shared__ unsigned long long mbars[2];
    __shared__ bool     sLast;

    const int tid = threadIdx.x;
    if (tid < 5) {
        int p = tid; unsigned w = 0;
        for (int i = 0; i < 4; i++) {
            int dnm = p + 3 - i;
            unsigned t = (dnm > 0) ? (unsigned)((60 * i) / dnm) : 0u;
            w |= (t & 0xFFu) << (8 * i);
        }
        sT60[p] = w;
    }
    if (tid < 16) {
        int p = (tid >> 2) + 1, q = (tid & 3) + 1;
        double r = 1.0 / (((double)p + 12e-6) * ((double)q + 12e-6));
        unsigned R30 = (unsigned)__double2ll_rn(r * 1073741824.0);
        unsigned A30 = (unsigned)__double2ll_rn((1e-6 * (p + q) + 1.2e-11) * r * 1073741824.0);
        sSim[p * 4 + q] = make_uint2(R30, A30);
    }

    const int lane = tid & 31;
    const int wid  = tid >> 5;
    const bool laneOwn = (lane < 29);

    // balanced contiguous tile range for this block
    const int nB   = gridDim.x;
    const int tBeg = (int)(((long long)blockIdx.x       * nTiles) / nB);
    const int tEnd = (int)(((long long)(blockIdx.x + 1) * nTiles) / nB);
    const int nT   = tEnd - tBeg;

    const uint32_t mb0 = smem_u32(&mbars[0]);
    const uint32_t mb1 = smem_u32(&mbars[1]);
    const uint32_t dynBase = smem_u32(dynS);

    if (tid == 0 && nT > 0) { mbar_init(mb0, 1); mbar_init(mb1, 1); }
    __syncthreads();

    if (tid == 0 && nT > 0) {
        fence_async();
        // prologue: tiles tBeg -> buf0, tBeg+1 -> buf1
        #pragma unroll 1
        for (int j = 0; j < 2 && j < nT; j++) {
            int t = tBeg + j;
            int base = t * TILE_ROWS;
            int rows = T - base; if (rows > COPY_ROWS) rows = COPY_ROWS;
            unsigned bytes = (unsigned)rows * 16u;
            uint32_t mb = j ? mb1 : mb0;
            uint32_t d0 = dynBase + (unsigned)j * (2u * TILE_BYTES);
            mbar_expect_tx(mb, 2u * bytes);
            bulk_copy(d0,              pred + base, bytes, mb);
            bulk_copy(d0 + TILE_BYTES, targ + base, bytes, mb);
        }
    }

    unsigned long long simAcc = 0ull;
    unsigned penAcc = 0u;
    unsigned ph0 = 0, ph1 = 0;
    const int localRow = wid * 29 + lane;
    const int lastWin = T - 4;

    for (int k = 0; k < nT; k++) {
        const int buf = k & 1;
        mbar_wait(buf ? mb1 : mb0, buf ? ph1 : ph0);
        if (buf) ph1 ^= 1; else ph0 ^= 1;

        const int t = tBeg + k;
        const float4* ps = (const float4*)(dynS + buf * (2 * TILE_BYTES));
        const float4* ts = (const float4*)(dynS + buf * (2 * TILE_BYTES) + TILE_BYTES);
        float4 pv = ps[localRow];                  // LDS.128, conflict-free
        float4 tv = ts[localRow];
        const int r = t * TILE_ROWS + localRow;

        unsigned pm = pcmask(pv);
        unsigned tm = pcmask(tv);
        int p  = __popc(pm); p = (p < 4) ? p : 4;  // clamp: stale smem safety
        int q  = __popc(tm); q = (q < 4) ? q : 4;
        int it = __popc(pm & tm);

        uint2 ra = sSim[p * 4 + q];
        if (laneOwn && (r < T))
            simAcc += (unsigned long long)((unsigned)it * ra.x + ra.y);

        unsigned Tp = sT60[p];
        unsigned iM0 = __popc(pm & 0x091u), iM1 = __popc(pm & 0x221u), iM2 = __popc(pm & 0x884u);
        unsigned im0 = __popc(pm & 0x089u), im1 = __popc(pm & 0x121u), im2 = __popc(pm & 0x484u);
        unsigned selP = iM0 | (im0 << 4) | (iM2 << 8) | (im2 << 12);
        unsigned selQ = iM1 | (im1 << 4);
        unsigned P = __byte_perm(Tp, 0, selP);     // {tM0, tm0, tM2, tm2}
        unsigned Q = __byte_perm(Tp, 0, selQ);     // {tM1, tm1, -, -}

        unsigned Q1 = __shfl_down_sync(0xffffffffu, Q, 1);
        unsigned P2 = __shfl_down_sync(0xffffffffu, P, 2);
        unsigned P3 = __shfl_down_sync(0xffffffffu, P, 3);

        unsigned v1 = __byte_perm(P,  Q1, 0x0040);
        unsigned v2 = __byte_perm(P2, P3, 0x0042);
        unsigned majW = __byte_perm(v1, v2, 0x5410);
        unsigned w1 = __byte_perm(P,  Q1, 0x0051);
        unsigned w2 = __byte_perm(P2, P3, 0x0053);
        unsigned minW = __byte_perm(w1, w2, 0x5410);

        unsigned SM = __dp4a(majW, 0x01010101u, 0u);
        unsigned Sm = __dp4a(minW, 0x01010101u, 0u);
        if (laneOwn && (r <= lastWin))
            penAcc += (SM > Sm) ? SM : Sm;         // 240*(1-min(maj,mino))

        __syncthreads();                           // all done reading buf
        if (tid == 0 && (k + 2 < nT)) {
            int tn = t + 2;
            int base = tn * TILE_ROWS;
            int rows = T - base; if (rows > COPY_ROWS) rows = COPY_ROWS;
            unsigned bytes = (unsigned)rows * 16u;
            uint32_t mb = buf ? mb1 : mb0;
            uint32_t d0 = dynBase + (unsigned)buf * (2u * TILE_BYTES);
            fence_async();
            mbar_expect_tx(mb, 2u * bytes);
            bulk_copy(d0,              pred + base, bytes, mb);
            bulk_copy(d0 + TILE_BYTES, targ + base, bytes, mb);
        }
    }

    // warp reduction (exact integers -> order-independent)
    unsigned long long penW = (unsigned long long)penAcc;
    #pragma unroll
    for (int o = 16; o; o >>= 1) {
        simAcc += __shfl_xor_sync(0xffffffffu, simAcc, o);
        penW   += __shfl_xor_sync(0xffffffffu, penW,   o);
    }
    if (lane == 0) { redS[wid] = simAcc; redP[wid] = penW; }
    __syncthreads();

    if (wid == 0) {
        unsigned long long s = redS[lane];
        unsigned long long p = redP[lane];
        #pragma unroll
        for (int o = 16; o; o >>= 1) {
            s += __shfl_xor_sync(0xffffffffu, s, o);
            p += __shfl_xor_sync(0xffffffffu, p, o);
        }
        if (lane == 0) {
            int slot = blockIdx.x & 31;
            atomicAdd(&g_simSlots[slot], s);
            atomicAdd(&g_penSlots[slot], p);
            __threadfence();
            sLast = (atomicAdd(&g_count, 1u) == gridDim.x - 1);
        }
    }
    __syncthreads();

    if (sLast && wid == 0) {
        __threadfence();
        unsigned long long s = *(volatile unsigned long long*)&g_simSlots[lane];
        unsigned long long p = *(volatile unsigned long long*)&g_penSlots[lane];
        #pragma unroll
        for (int o = 16; o; o >>= 1) {
            s += __shfl_xor_sync(0xffffffffu, s, o);
            p += __shfl_xor_sync(0xffffffffu, p, o);
        }
        if (lane == 0) {
            double simMean = ((double)s * (1.0 / 1073741824.0)) / (double)T;
            long long nWin = (long long)T - 3;
            double pen = (nWin > 0) ? (0.5 - (double)p / (480.0 * (double)nWin)) : 0.0;
            out[0] = (float)((1.0 - simMean) + pen);
        }
        g_simSlots[lane] = 0ull;   // self-reset for graph replay
        g_penSlots[lane] = 0ull;
        if (lane == 0) g_count = 0;
    }
}

extern "C" void kernel_launch(void* const* d_in, const int* in_sizes, int n_in,
                              void* d_out, int out_size)
{
    const float4* pred = (const float4*)d_in[0];
    const float4* targ = (const float4*)d_in[1];
    int T1 = in_sizes[0] / 4;
    int T2 = in_sizes[1] / 4;
    int T = (T1 < T2) ? T1 : T2;

    int nChunks = (T + 28) / 29;
    if (nChunks < 1) nChunks = 1;
    int nTiles = (nChunks + WPB - 1) / WPB;
    int blocks = (nTiles < NBLK) ? nTiles : NBLK;

    cudaFuncSetAttribute(chord_fused,
                         cudaFuncAttributeMaxDynamicSharedMemorySize, DYN_SMEM);
    chord_fused<<<blocks, THREADS, DYN_SMEM>>>(pred, targ, (float*)d_out, T, nTiles);
}

// round 14
// speedup vs baseline: 1.1165x; 1.1165x over previous
#include <cuda_runtime.h>

// ---------------------------------------------------------------------------
// ChordProgressionLoss v14 — R12 frame + instruction diet.
//   * scalar magic-add pcmask (f32x2 pack/unpack movs cost more than saved)
//   * interior/tail split: fast loop has ZERO bounds checks (chunk base
//     <= T-32 guarantees loads and window rows in range); the <=3 tail
//     chunks are handled by global warp 0 with full guards.
//   * pointer-increment addressing (no per-iter index->address IMADs).
// Math identical: magic masks, PRMT jaccard bytes, 3 shuffles + dp4a
// windows, integer max, fixed-point sim. Exact -> deterministic atomics.
// 296 blocks x 1024 threads (2/SM), grid-stride by 9472 chunks.
// ---------------------------------------------------------------------------

#define NBLK 296
#define THREADS 1024
#define WPB 32

__device__ unsigned long long g_simSlots[32];
__device__ unsigned long long g_penSlots[32];
__device__ unsigned int       g_count = 0;

__device__ __forceinline__ unsigned pcbit(float f) {
    unsigned b1 = __float_as_uint(f + 12582912.0f);          // low bits = iv
    float t = fmaf(f, 0.0833333358f, -0.45833334f);
    unsigned b2 = __float_as_uint(t + 12582912.0f);          // low bits = iv/12
    return 1u << ((b1 - 12u * b2) & 31u);                    // low5 = iv%12
}
__device__ __forceinline__ unsigned pcmask(float4 v) {
    return pcbit(v.x) | pcbit(v.y) | pcbit(v.z) | pcbit(v.w);
}

// core per-chunk math; adds guarded by caller-supplied predicates
__device__ __forceinline__ void chunkMath(
    unsigned pm, unsigned tm, bool simOwn, bool penOwn,
    const unsigned* __restrict__ sT60, const uint2* __restrict__ sSim,
    unsigned long long& simAcc, unsigned& penAcc)
{
    int p  = __popc(pm);                      // 1..4
    int q  = __popc(tm);
    int it = __popc(pm & tm);

    uint2 ra = sSim[p * 4 + q];
    if (simOwn) simAcc += (unsigned long long)((unsigned)it * ra.x + ra.y);

    unsigned Tp = sT60[p];
    unsigned iM0 = __popc(pm & 0x091u), iM1 = __popc(pm & 0x221u), iM2 = __popc(pm & 0x884u);
    unsigned im0 = __popc(pm & 0x089u), im1 = __popc(pm & 0x121u), im2 = __popc(pm & 0x484u);
    unsigned selP = iM0 | (im0 << 4) | (iM2 << 8) | (im2 << 12);
    unsigned selQ = iM1 | (im1 << 4);
    unsigned P = __byte_perm(Tp, 0, selP);    // {tM0, tm0, tM2, tm2}
    unsigned Q = __byte_perm(Tp, 0, selQ);    // {tM1, tm1, -, -}

    unsigned Q1 = __shfl_down_sync(0xffffffffu, Q, 1);
    unsigned P2 = __shfl_down_sync(0xffffffffu, P, 2);
    unsigned P3 = __shfl_down_sync(0xffffffffu, P, 3);

    unsigned v1 = __byte_perm(P,  Q1, 0x0040);
    unsigned v2 = __byte_perm(P2, P3, 0x0042);
    unsigned majW = __byte_perm(v1, v2, 0x5410);
    unsigned w1 = __byte_perm(P,  Q1, 0x0051);
    unsigned w2 = __byte_perm(P2, P3, 0x0053);
    unsigned minW = __byte_perm(w1, w2, 0x5410);

    unsigned SM = __dp4a(majW, 0x01010101u, 0u);
    unsigned Sm = __dp4a(minW, 0x01010101u, 0u);
    if (penOwn) penAcc += (SM > Sm) ? SM : Sm;   // 240*(1-min(maj,mino))
}

__global__ __launch_bounds__(THREADS, 2) void chord_fused(
    const float4* __restrict__ pred, const float4* __restrict__ targ,
    float* __restrict__ out, int T, int nFast, int nChunks)
{
    __shared__ unsigned sT60[5];
    __shared__ uint2    sSim[21];
    __shared__ unsigned long long redS[WPB], redP[WPB];
    __shared__ bool     sLast;

    const int tid = threadIdx.x;
    if (tid < 5) {
        int p = tid; unsigned w = 0;
        for (int i = 0; i < 4; i++) {
            int dnm = p + 3 - i;
            unsigned t = (dnm > 0) ? (unsigned)((60 * i) / dnm) : 0u;
            w |= (t & 0xFFu) << (8 * i);
        }
        sT60[p] = w;
    }
    if (tid < 16) {
        int p = (tid >> 2) + 1, q = (tid & 3) + 1;
        double r = 1.0 / (((double)p + 12e-6) * ((double)q + 12e-6));
        unsigned R30 = (unsigned)__double2ll_rn(r * 1073741824.0);
        unsigned A30 = (unsigned)__double2ll_rn((1e-6 * (p + q) + 1.2e-11) * r * 1073741824.0);
        sSim[p * 4 + q] = make_uint2(R30, A30);
    }
    __syncthreads();

    const int lane = tid & 31;
    const int wid  = tid >> 5;
    const bool laneOwn = (lane < 29);
    const int  W  = blockIdx.x * WPB + wid;     // global warp id
    const int  NW = NBLK * WPB;                 // 9472

    unsigned long long simAcc = 0ull;
    unsigned penAcc = 0u;

    // ---- fast interior loop: no bounds checks, pointer-stride addressing ----
    {
        const float4* pp = pred + (W * 29 + lane);
        const float4* tp = targ + (W * 29 + lane);
        const long long step = (long long)NW * 29;
        int u = W;
        #pragma unroll 1
        while (u < nFast) {
            float4 pv = *pp;
            float4 tv = *tp;
            unsigned pm = pcmask(pv);
            unsigned tm = pcmask(tv);
            chunkMath(pm, tm, laneOwn, laneOwn, sT60, sSim, simAcc, penAcc);
            pp += step; tp += step;
            u += NW;
        }
    }

    // ---- tail: global warp 0 handles chunks [nFast, nChunks) with guards ----
    if (W == 0) {
        const int rMax = (T > 0) ? (T - 1) : 0;
        const int lastWin = T - 4;
        for (int u = nFast; u < nChunks; u++) {
            const int r = u * 29 + lane;
            const int c = (r < rMax) ? r : rMax;
            float4 pv = pred[c];
            float4 tv = targ[c];
            unsigned pm = pcmask(pv);
            unsigned tm = pcmask(tv);
            chunkMath(pm, tm, laneOwn && (r < T), laneOwn && (r <= lastWin),
                      sT60, sSim, simAcc, penAcc);
        }
    }

    // warp reduction (exact integers -> order-independent)
    unsigned long long penW = (unsigned long long)penAcc;
    #pragma unroll
    for (int o = 16; o; o >>= 1) {
        simAcc += __shfl_xor_sync(0xffffffffu, simAcc, o);
        penW   += __shfl_xor_sync(0xffffffffu, penW,   o);
    }
    if (lane == 0) { redS[wid] = simAcc; redP[wid] = penW; }
    __syncthreads();

    if (wid == 0) {
        unsigned long long s = redS[lane];
        unsigned long long p = redP[lane];
        #pragma unroll
        for (int o = 16; o; o >>= 1) {
            s += __shfl_xor_sync(0xffffffffu, s, o);
            p += __shfl_xor_sync(0xffffffffu, p, o);
        }
        if (lane == 0) {
            int slot = blockIdx.x & 31;
            atomicAdd(&g_simSlots[slot], s);
            atomicAdd(&g_penSlots[slot], p);
            __threadfence();
            sLast = (atomicAdd(&g_count, 1u) == gridDim.x - 1);
        }
    }
    __syncthreads();

    if (sLast && wid == 0) {
        __threadfence();
        unsigned long long s = *(volatile unsigned long long*)&g_simSlots[lane];
        unsigned long long p = *(volatile unsigned long long*)&g_penSlots[lane];
        #pragma unroll
        for (int o = 16; o; o >>= 1) {
            s += __shfl_xor_sync(0xffffffffu, s, o);
            p += __shfl_xor_sync(0xffffffffu, p, o);
        }
        if (lane == 0) {
            double simMean = ((double)s * (1.0 / 1073741824.0)) / (double)T;
            long long nWin = (long long)T - 3;
            double pen = (nWin > 0) ? (0.5 - (double)p / (480.0 * (double)nWin)) : 0.0;
            out[0] = (float)((1.0 - simMean) + pen);
        }
        g_simSlots[lane] = 0ull;   // self-reset for graph replay
        g_penSlots[lane] = 0ull;
        if (lane == 0) g_count = 0;
    }
}

extern "C" void kernel_launch(void* const* d_in, const int* in_sizes, int n_in,
                              void* d_out, int out_size)
{
    const float4* pred = (const float4*)d_in[0];
    const float4* targ = (const float4*)d_in[1];
    int T1 = in_sizes[0] / 4;
    int T2 = in_sizes[1] / 4;
    int T = (T1 < T2) ? T1 : T2;

    int nChunks = (T + 28) / 29;
    if (nChunks < 1) nChunks = 1;
    // fast chunk u: loads rows u*29+lane (lane<=31) and owns windows up to
    // u*29+28; safe iff u*29 <= T-32  (covers both load and window bounds)
    int nFast = (T >= 32) ? ((T - 32) / 29 + 1) : 0;
    if (nFast > nChunks) nFast = nChunks;

    chord_fused<<<NBLK, THREADS>>>(pred, targ, (float*)d_out, T, nFast, nChunks);
}